// round 15
// baseline (speedup 1.0000x reference)
#include <cuda_runtime.h>
#include <cuda_bf16.h>
#include <cstdint>

// LayerHypercube: out[b, f*1024+o] = sum_j x[b, o^(1<<j)] * w[f,j,o] + bias[f,o] + x[b,o]
// B=2048, F=16, O=IN=1024, BITS=10. fm[f,j,o] == o^(1<<j) (computed, not loaded).
//
// R15 = R14 (2o x 4fm layout, shfl j=1..5, LDS.64 j=6..9, phase-cooperative
//            staging with 1 barrier/phase, f32x2 math, __stcs stores)
//   + software pipelining: p/q of pair i+1 prefetched during pair i compute.

#define BATCH   2048
#define INSZ    1024
#define OUTSZ   1024
#define NFM     16
#define NBITS   10

#define THREADS 128
#define NWARP   4
#define OTILE   64
#define ROWS    32              // 16 pairs per block
#define PAIRS   (ROWS / 2)
#define PPH     4               // pairs per phase (one per warp)
#define PHASES  (PAIRS / PPH)   // 4
#define OBLOCKS (OUTSZ / OTILE) // 16
#define BBLOCKS (BATCH / ROWS)  // 64
#define NBUF    3               // phase buffers

#define CHUNK_B   256
#define ROW_B     (5 * CHUNK_B)     // 1280 B per row (own + 4 remote chunks)
#define PBUF_B    (2 * ROW_B)       // 2560 B per pair
#define PHASE_B   (PPH * PBUF_B)    // 10240 B per phase

typedef unsigned long long ull;

__device__ __forceinline__ void cp16(uint32_t dst_smem, const void* src_gmem) {
    asm volatile("cp.async.cg.shared.global [%0], [%1], 16;\n"
                 :: "r"(dst_smem), "l"(src_gmem));
}
__device__ __forceinline__ void cp_commit() { asm volatile("cp.async.commit_group;\n"); }
__device__ __forceinline__ void cp_wait1()  { asm volatile("cp.async.wait_group 1;\n"); }

__device__ __forceinline__ void fma2(ull& d, ull a, ull b) {
    asm("fma.rn.f32x2 %0, %1, %2, %0;" : "+l"(d) : "l"(a), "l"(b));
}
__device__ __forceinline__ ull add2(ull a, ull b) {
    ull d; asm("add.rn.f32x2 %0, %1, %2;" : "=l"(d) : "l"(a), "l"(b)); return d;
}
__device__ __forceinline__ ull pk(float lo, float hi) {
    ull d; asm("mov.b64 %0, {%1, %2};" : "=l"(d) : "f"(lo), "f"(hi)); return d;
}
__device__ __forceinline__ void stcs1(void* p, ull v) {
    asm volatile("st.global.cs.b64 [%0], %1;" :: "l"(p), "l"(v));
}

__global__ __launch_bounds__(THREADS, 4)
void hypercube_kernel(const float* __restrict__ x,
                      const float* __restrict__ w,
                      const float* __restrict__ bias,
                      float* __restrict__ out)
{
    __shared__ float4 sbuf[NBUF * (PHASE_B / 16)];   // 30720 B

    const int tid   = threadIdx.x;
    const int lane  = tid & 31;
    const int wid   = tid >> 5;
    const int o2    = lane;            // o-pair index within the tile (0..31)
    const int fq    = wid;             // fm quad: fm = 4*fq + m
    const int row0  = blockIdx.y * ROWS;
    const int B0    = blockIdx.x * OTILE;
    const int ob2   = B0 + o2 * 2;     // this thread's o base (2 consecutive o)

    // ---- weights & bias -> registers as f32x2 (80 + 8 regs) ----
    ull wf[4][NBITS];
    ull bb[4];
#pragma unroll
    for (int m = 0; m < 4; m++) {
        const int fm = 4 * fq + m;
#pragma unroll
        for (int j = 0; j < NBITS; j++)
            wf[m][j] = *reinterpret_cast<const ull*>(w + ((fm * NBITS + j) * OUTSZ + ob2));
        bb[m] = *reinterpret_cast<const ull*>(bias + fm * OUTSZ + ob2);
    }

    // ---- staging unit map: 160 16B units/pair, 5 per lane ----
    int srcOff[5];
    {
        const int tb = B0 * 4;   // tile byte offset within a row
#pragma unroll
        for (int k = 0; k < 5; k++) {
            const int u = k * 32 + lane;
            const int r = (u >= 80) ? 1 : 0;
            const int t = u - 80 * r;
            const int c = t >> 4;
            const int i = t & 15;
            const int xorB = (c == 0) ? 0 : (256 << (c - 1));  // 0,256,512,1024,2048 B
            srcOff[k] = r * 4096 + (tb ^ xorB) + i * 16;
        }
    }

    const uint32_t sbase = (uint32_t)__cvta_generic_to_shared(sbuf);
    const char*    xpb   = reinterpret_cast<const char*>(x + (size_t)row0 * INSZ);

    // warp wid stages pair (ph*PPH + wid) into slot [ph%3][wid]
    auto issue_phase = [&](int ph) {
        const char* base = xpb + (size_t)(ph * PPH + wid) * 8192;
        const uint32_t db = sbase + (ph % NBUF) * PHASE_B + wid * PBUF_B + lane * 16;
#pragma unroll
        for (int k = 0; k < 5; k++)
            cp16(db + k * 512, base + srcOff[k]);
    };

    issue_phase(0); cp_commit();
    issue_phase(1); cp_commit();

    float* op = out + (size_t)row0 * (NFM * OUTSZ) + (4 * fq) * OUTSZ + ob2;

    for (int ph = 0; ph < PHASES; ph++) {
        cp_wait1();            // this warp's copies for phase ph complete
        __syncthreads();       // all warps' copies complete; phase ph-1 reads done

        if (ph + 2 < PHASES) issue_phase(ph + 2);
        cp_commit();           // uniform group accounting

        const char* pb = reinterpret_cast<const char*>(sbuf) + (ph % NBUF) * PHASE_B;

        // prefetch pair 0 own values
        float2 pc = *reinterpret_cast<const float2*>(pb + o2 * 8);
        float2 qc = *reinterpret_cast<const float2*>(pb + ROW_B + o2 * 8);

#pragma unroll
        for (int i = 0; i < PPH; i++) {
            const char* rbA = pb + i * PBUF_B;          // row A chunks
            const char* rbB = rbA + ROW_B;              // row B chunks

            const float2 p = pc;
            const float2 q = qc;

            // prefetch next pair's own values (overlaps with this pair's math)
            if (i + 1 < PPH) {
                const char* nA = pb + (i + 1) * PBUF_B;
                pc = *reinterpret_cast<const float2*>(nA + o2 * 8);
                qc = *reinterpret_cast<const float2*>(nA + ROW_B + o2 * 8);
            }

            // j=6..9 operands: issue LDS early so scoreboards fill under shfl
            ull U6, V6, U7, V7, U8, V8, U9, V9;
            {
                U6 = *reinterpret_cast<const ull*>(rbA + 1 * CHUNK_B + o2 * 8);
                V6 = *reinterpret_cast<const ull*>(rbB + 1 * CHUNK_B + o2 * 8);
                U7 = *reinterpret_cast<const ull*>(rbA + 2 * CHUNK_B + o2 * 8);
                V7 = *reinterpret_cast<const ull*>(rbB + 2 * CHUNK_B + o2 * 8);
                U8 = *reinterpret_cast<const ull*>(rbA + 3 * CHUNK_B + o2 * 8);
                V8 = *reinterpret_cast<const ull*>(rbB + 3 * CHUNK_B + o2 * 8);
                U9 = *reinterpret_cast<const ull*>(rbA + 4 * CHUNK_B + o2 * 8);
                V9 = *reinterpret_cast<const ull*>(rbB + 4 * CHUNK_B + o2 * 8);
            }

            const ull P = pk(p.x, p.y), Q = pk(q.x, q.y);
            const ull Psw = pk(p.y, p.x), Qsw = pk(q.y, q.x);

            // acc = bias + tiled x ; then j=0 (x[o^1] = swapped own pair)
            ull a[4], c[4];
#pragma unroll
            for (int m = 0; m < 4; m++) {
                a[m] = add2(bb[m], P);
                c[m] = add2(bb[m], Q);
                fma2(a[m], wf[m][0], Psw);
                fma2(c[m], wf[m][0], Qsw);
            }

            // j=1..5: lane XOR 1,2,4,8,16 -> shfl.bfly of own float2
#pragma unroll
            for (int j = 1; j < 6; j++) {
                const int msk = 1 << (j - 1);
                const float ux = __shfl_xor_sync(0xffffffffu, p.x, msk);
                const float uy = __shfl_xor_sync(0xffffffffu, p.y, msk);
                const float vx = __shfl_xor_sync(0xffffffffu, q.x, msk);
                const float vy = __shfl_xor_sync(0xffffffffu, q.y, msk);
                const ull U = pk(ux, uy), V = pk(vx, vy);
#pragma unroll
                for (int m = 0; m < 4; m++) {
                    fma2(a[m], wf[m][j], U);
                    fma2(c[m], wf[m][j], V);
                }
            }

            // j=6..9: consume the early LDS results
#pragma unroll
            for (int m = 0; m < 4; m++) {
                fma2(a[m], wf[m][6], U6);  fma2(c[m], wf[m][6], V6);
                fma2(a[m], wf[m][7], U7);  fma2(c[m], wf[m][7], V7);
                fma2(a[m], wf[m][8], U8);  fma2(c[m], wf[m][8], V8);
                fma2(a[m], wf[m][9], U9);  fma2(c[m], wf[m][9], V9);
            }

            // stores: 8 x STG.64, perfectly coalesced across the warp
#pragma unroll
            for (int m = 0; m < 4; m++) {
                stcs1(op + m * OUTSZ,               a[m]);
                stcs1(op + NFM * OUTSZ + m * OUTSZ, c[m]);
            }

            op += 2 * NFM * OUTSZ;
        }
    }
}

extern "C" void kernel_launch(void* const* d_in, const int* in_sizes, int n_in,
                              void* d_out, int out_size)
{
    const float* x    = (const float*)d_in[0];
    const float* w    = (const float*)d_in[1];
    const float* bias = (const float*)d_in[2];
    // d_in[3] = fm (int32) — values are o^(1<<j), computed inline instead.
    float* out = (float*)d_out;

    dim3 grid(OBLOCKS, BBLOCKS);
    hypercube_kernel<<<grid, THREADS>>>(x, w, bias, out);
}

// round 16
// speedup vs baseline: 1.0048x; 1.0048x over previous
#include <cuda_runtime.h>
#include <cuda_bf16.h>
#include <cstdint>

// LayerHypercube: out[b, f*1024+o] = sum_j x[b, o^(1<<j)] * w[f,j,o] + bias[f,o] + x[b,o]
// B=2048, F=16, O=IN=1024, BITS=10. fm[f,j,o] == o^(1<<j) (computed, not loaded).
//
// R16 = R15 body (2o x 4fm, shfl j=1..5, LDS.64 j=6..9, phase staging,
//       software pipelining, f32x2, __stcs)
//   + persistent single-wave grid: 16 x 37 = 592 blocks (=148 SMs x 4 CTAs),
//     block strides batch pairs t -> pair index by + 37*t. Weights load once
//     per block (prologue count -42%), no second wave.

#define BATCH   2048
#define INSZ    1024
#define OUTSZ   1024
#define NFM     16
#define NBITS   10

#define THREADS 128
#define NWARP   4
#define OTILE   64
#define OBLOCKS (OUTSZ / OTILE) // 16
#define BGRID   37              // batch-dimension grid -> 16*37 = 592 blocks
#define TOTPAIRS (BATCH / 2)    // 1024 pairs per o-column
#define PPH     4               // pairs per phase (one per warp)
#define PH_MAX  7               // ceil(28/4); t_count is 27 or 28 for all blocks
#define NBUF    3               // phase buffers

#define CHUNK_B   256
#define ROW_B     (5 * CHUNK_B)     // 1280 B per row (own + 4 remote chunks)
#define PBUF_B    (2 * ROW_B)       // 2560 B per pair
#define PHASE_B   (PPH * PBUF_B)    // 10240 B per phase

typedef unsigned long long ull;

__device__ __forceinline__ void cp16(uint32_t dst_smem, const void* src_gmem) {
    asm volatile("cp.async.cg.shared.global [%0], [%1], 16;\n"
                 :: "r"(dst_smem), "l"(src_gmem));
}
__device__ __forceinline__ void cp_commit() { asm volatile("cp.async.commit_group;\n"); }
__device__ __forceinline__ void cp_wait1()  { asm volatile("cp.async.wait_group 1;\n"); }

__device__ __forceinline__ void fma2(ull& d, ull a, ull b) {
    asm("fma.rn.f32x2 %0, %1, %2, %0;" : "+l"(d) : "l"(a), "l"(b));
}
__device__ __forceinline__ ull add2(ull a, ull b) {
    ull d; asm("add.rn.f32x2 %0, %1, %2;" : "=l"(d) : "l"(a), "l"(b)); return d;
}
__device__ __forceinline__ ull pk(float lo, float hi) {
    ull d; asm("mov.b64 %0, {%1, %2};" : "=l"(d) : "f"(lo), "f"(hi)); return d;
}
__device__ __forceinline__ void stcs1(void* p, ull v) {
    asm volatile("st.global.cs.b64 [%0], %1;" :: "l"(p), "l"(v));
}

__global__ __launch_bounds__(THREADS, 4)
void hypercube_kernel(const float* __restrict__ x,
                      const float* __restrict__ w,
                      const float* __restrict__ bias,
                      float* __restrict__ out)
{
    __shared__ float4 sbuf[NBUF * (PHASE_B / 16)];   // 30720 B

    const int tid   = threadIdx.x;
    const int lane  = tid & 31;
    const int wid   = tid >> 5;
    const int o2    = lane;            // o-pair index within the tile (0..31)
    const int fq    = wid;             // fm quad: fm = 4*fq + m
    const int by    = blockIdx.y;      // 0..36
    const int B0    = blockIdx.x * OTILE;
    const int ob2   = B0 + o2 * 2;     // this thread's o base (2 consecutive o)

    // number of pair-work-items for this block: t with by + 37*t < 1024
    const int t_count = (TOTPAIRS - by + BGRID - 1) / BGRID;   // 27 or 28

    // ---- weights & bias -> registers as f32x2 (loaded ONCE per block) ----
    ull wf[4][NBITS];
    ull bb[4];
#pragma unroll
    for (int m = 0; m < 4; m++) {
        const int fm = 4 * fq + m;
#pragma unroll
        for (int j = 0; j < NBITS; j++)
            wf[m][j] = *reinterpret_cast<const ull*>(w + ((fm * NBITS + j) * OUTSZ + ob2));
        bb[m] = *reinterpret_cast<const ull*>(bias + fm * OUTSZ + ob2);
    }

    // ---- staging unit map: 160 16B units/pair, 5 per lane ----
    int srcOff[5];
    {
        const int tb = B0 * 4;   // tile byte offset within a row
#pragma unroll
        for (int k = 0; k < 5; k++) {
            const int u = k * 32 + lane;
            const int r = (u >= 80) ? 1 : 0;
            const int t = u - 80 * r;
            const int c = t >> 4;
            const int i = t & 15;
            const int xorB = (c == 0) ? 0 : (256 << (c - 1));  // 0,256,512,1024,2048 B
            srcOff[k] = r * 4096 + (tb ^ xorB) + i * 16;
        }
    }

    const uint32_t sbase = (uint32_t)__cvta_generic_to_shared(sbuf);
    const char*    xb    = reinterpret_cast<const char*>(x);

    // warp wid stages work-item t = ph*4 + wid (pair index by + 37*t)
    auto issue_phase = [&](int ph) {
        const int t = ph * PPH + wid;
        if (t < t_count) {
            const char* base = xb + (size_t)(by + BGRID * t) * 8192;
            const uint32_t db = sbase + (ph % NBUF) * PHASE_B + wid * PBUF_B + lane * 16;
#pragma unroll
            for (int k = 0; k < 5; k++)
                cp16(db + k * 512, base + srcOff[k]);
        }
    };

    issue_phase(0); cp_commit();
    issue_phase(1); cp_commit();

    // output: for work-item t, rows 2*(by+37t), 2*(by+37t)+1
    float* opBase = out + (size_t)(2 * by) * (NFM * OUTSZ) + (4 * fq) * OUTSZ + ob2;
    const size_t OP_T = (size_t)(2 * BGRID) * (NFM * OUTSZ);   // stride per t

    for (int ph = 0; ph < PH_MAX; ph++) {
        cp_wait1();            // this warp's copies for phase ph complete
        __syncthreads();       // all warps' copies complete; phase ph-1 reads done

        issue_phase(ph + 2);   // internally bounded by t_count
        cp_commit();           // uniform group accounting

        const char* pb = reinterpret_cast<const char*>(sbuf) + (ph % NBUF) * PHASE_B;

        // prefetch pair 0 own values
        float2 pc = *reinterpret_cast<const float2*>(pb + o2 * 8);
        float2 qc = *reinterpret_cast<const float2*>(pb + ROW_B + o2 * 8);

#pragma unroll
        for (int i = 0; i < PPH; i++) {
            const int t = ph * PPH + i;
            if (t >= t_count) break;

            const char* rbA = pb + i * PBUF_B;          // row A chunks
            const char* rbB = rbA + ROW_B;              // row B chunks

            const float2 p = pc;
            const float2 q = qc;

            // prefetch next pair's own values (overlaps with this pair's math)
            if (i + 1 < PPH) {
                const char* nA = pb + (i + 1) * PBUF_B;
                pc = *reinterpret_cast<const float2*>(nA + o2 * 8);
                qc = *reinterpret_cast<const float2*>(nA + ROW_B + o2 * 8);
            }

            // j=6..9 operands: issue LDS early so scoreboards fill under shfl
            const ull U6 = *reinterpret_cast<const ull*>(rbA + 1 * CHUNK_B + o2 * 8);
            const ull V6 = *reinterpret_cast<const ull*>(rbB + 1 * CHUNK_B + o2 * 8);
            const ull U7 = *reinterpret_cast<const ull*>(rbA + 2 * CHUNK_B + o2 * 8);
            const ull V7 = *reinterpret_cast<const ull*>(rbB + 2 * CHUNK_B + o2 * 8);
            const ull U8 = *reinterpret_cast<const ull*>(rbA + 3 * CHUNK_B + o2 * 8);
            const ull V8 = *reinterpret_cast<const ull*>(rbB + 3 * CHUNK_B + o2 * 8);
            const ull U9 = *reinterpret_cast<const ull*>(rbA + 4 * CHUNK_B + o2 * 8);
            const ull V9 = *reinterpret_cast<const ull*>(rbB + 4 * CHUNK_B + o2 * 8);

            const ull P = pk(p.x, p.y), Q = pk(q.x, q.y);
            const ull Psw = pk(p.y, p.x), Qsw = pk(q.y, q.x);

            // acc = bias + tiled x ; then j=0 (x[o^1] = swapped own pair)
            ull a[4], c[4];
#pragma unroll
            for (int m = 0; m < 4; m++) {
                a[m] = add2(bb[m], P);
                c[m] = add2(bb[m], Q);
                fma2(a[m], wf[m][0], Psw);
                fma2(c[m], wf[m][0], Qsw);
            }

            // j=1..5: lane XOR 1,2,4,8,16 -> shfl.bfly of own float2
#pragma unroll
            for (int j = 1; j < 6; j++) {
                const int msk = 1 << (j - 1);
                const float ux = __shfl_xor_sync(0xffffffffu, p.x, msk);
                const float uy = __shfl_xor_sync(0xffffffffu, p.y, msk);
                const float vx = __shfl_xor_sync(0xffffffffu, q.x, msk);
                const float vy = __shfl_xor_sync(0xffffffffu, q.y, msk);
                const ull U = pk(ux, uy), V = pk(vx, vy);
#pragma unroll
                for (int m = 0; m < 4; m++) {
                    fma2(a[m], wf[m][j], U);
                    fma2(c[m], wf[m][j], V);
                }
            }

            // j=6..9: consume the early LDS results
#pragma unroll
            for (int m = 0; m < 4; m++) {
                fma2(a[m], wf[m][6], U6);  fma2(c[m], wf[m][6], V6);
                fma2(a[m], wf[m][7], U7);  fma2(c[m], wf[m][7], V7);
                fma2(a[m], wf[m][8], U8);  fma2(c[m], wf[m][8], V8);
                fma2(a[m], wf[m][9], U9);  fma2(c[m], wf[m][9], V9);
            }

            // stores: 8 x STG.64, perfectly coalesced across the warp
            float* op = opBase + (size_t)t * OP_T;
#pragma unroll
            for (int m = 0; m < 4; m++) {
                stcs1(op + m * OUTSZ,               a[m]);
                stcs1(op + NFM * OUTSZ + m * OUTSZ, c[m]);
            }
        }
    }
}

extern "C" void kernel_launch(void* const* d_in, const int* in_sizes, int n_in,
                              void* d_out, int out_size)
{
    const float* x    = (const float*)d_in[0];
    const float* w    = (const float*)d_in[1];
    const float* bias = (const float*)d_in[2];
    // d_in[3] = fm (int32) — values are o^(1<<j), computed inline instead.
    float* out = (float*)d_out;

    dim3 grid(OBLOCKS, BGRID);
    hypercube_kernel<<<grid, THREADS>>>(x, w, bias, out);
}